// round 2
// baseline (speedup 1.0000x reference)
#include <cuda_runtime.h>

// MxAssemble: out[b,c,y,x] = sum_{dy,dx in [0,13)} aff[b, dy*13+dx, y, x] * in2zp[b, c, y+dy-6, x+dx-6]
// B=4, D=169, C=64, H=W=192, fp32.

#define BB   4
#define CC   64
#define HH   192
#define WW   192
#define WIN  13
#define DD   169
#define HWSZ (HH*WW)

// Tiling
#define TW    64     // x pixels per block
#define TH    8      // y rows per block
#define CBLK  16     // channels per block
#define CPT   8      // channels per thread
#define XR    4      // x pixels per thread
#define SROWS (TH+12)   // 20
#define SCOLS (TW+12)   // 76
#define SPITCH 80       // smem row pitch in floats (16B-aligned rows)

__global__ __launch_bounds__(256, 2)
void mxassemble_kernel(const float* __restrict__ aff,
                       const float* __restrict__ in2,
                       float* __restrict__ out)
{
    __shared__ __align__(16) float s[CBLK][SROWS][SPITCH];

    const int tx = threadIdx.x;      // 0..15  -> x group
    const int ty = threadIdx.y;      // 0..15
    const int yy = ty & 7;           // row within tile
    const int ch = ty >> 3;          // channel half (0/1)

    const int bx = blockIdx.x;       // 12 = 4 cgroups * 3 xtiles, cgroup fastest
    const int cg = bx & 3;
    const int xt = bx >> 2;
    const int yt = blockIdx.y;       // 0..23
    const int b  = blockIdx.z;       // 0..3

    const int x0 = xt * TW;
    const int y0 = yt * TH;
    const int c0 = cg * CBLK;

    // ---- cooperative smem fill: in2[b, c0..c0+15, y0-6..y0+13, x0-6..x0+69], zero-padded
    {
        const float* in2b = in2 + (size_t)b * CC * HWSZ;
        const int tid = ty * 16 + tx;
        #pragma unroll 1
        for (int idx = tid; idx < CBLK * SROWS * SCOLS; idx += 256) {
            const int cc  = idx / (SROWS * SCOLS);
            const int rem = idx - cc * (SROWS * SCOLS);
            const int rr  = rem / SCOLS;
            const int col = rem - rr * SCOLS;
            const int gy = y0 - 6 + rr;
            const int gx = x0 - 6 + col;
            float v = 0.0f;
            if ((unsigned)gy < (unsigned)HH && (unsigned)gx < (unsigned)WW)
                v = in2b[(size_t)(c0 + cc) * HWSZ + gy * WW + gx];
            s[cc][rr][col] = v;
        }
    }
    __syncthreads();

    float acc[CPT][XR];
    #pragma unroll
    for (int c = 0; c < CPT; c++)
        #pragma unroll
        for (int i = 0; i < XR; i++) acc[c][i] = 0.0f;

    const int xs = tx * XR;  // base smem column for this thread's outputs
    const float* affp = aff + (size_t)b * DD * HWSZ + (y0 + yy) * WW + x0 + xs;

    #pragma unroll 1
    for (int dy = 0; dy < WIN; dy++) {
        // ---------- dx chunk 0: dx = 0..7 ----------
        float av[8][XR];
        #pragma unroll
        for (int j = 0; j < 8; j++) {
            const float4 a4 = *(const float4*)(affp + (size_t)(dy * WIN + j) * HWSZ);
            av[j][0] = a4.x; av[j][1] = a4.y; av[j][2] = a4.z; av[j][3] = a4.w;
        }
        #pragma unroll
        for (int c = 0; c < CPT; c++) {
            const float* srow = &s[ch * CPT + c][yy + dy][xs];
            float r[12];
            #pragma unroll
            for (int q = 0; q < 3; q++) {
                const float4 v = *(const float4*)(srow + q * 4);
                r[q*4+0] = v.x; r[q*4+1] = v.y; r[q*4+2] = v.z; r[q*4+3] = v.w;
            }
            #pragma unroll
            for (int j = 0; j < 8; j++)
                #pragma unroll
                for (int i = 0; i < XR; i++)
                    acc[c][i] = fmaf(av[j][i], r[i + j], acc[c][i]);
        }

        // ---------- dx chunk 1: dx = 8..12 ----------
        float av2[5][XR];
        #pragma unroll
        for (int j = 0; j < 5; j++) {
            const float4 a4 = *(const float4*)(affp + (size_t)(dy * WIN + 8 + j) * HWSZ);
            av2[j][0] = a4.x; av2[j][1] = a4.y; av2[j][2] = a4.z; av2[j][3] = a4.w;
        }
        #pragma unroll
        for (int c = 0; c < CPT; c++) {
            const float* srow = &s[ch * CPT + c][yy + dy][xs + 8];
            float r[8];
            #pragma unroll
            for (int q = 0; q < 2; q++) {
                const float4 v = *(const float4*)(srow + q * 4);
                r[q*4+0] = v.x; r[q*4+1] = v.y; r[q*4+2] = v.z; r[q*4+3] = v.w;
            }
            #pragma unroll
            for (int j = 0; j < 5; j++)
                #pragma unroll
                for (int i = 0; i < XR; i++)
                    acc[c][i] = fmaf(av2[j][i], r[i + j], acc[c][i]);
        }
    }

    // ---- write out: out[b, c0+ch*8+c, y0+yy, x0+xs .. +3]
    float* outp = out + (size_t)b * CC * HWSZ + (y0 + yy) * WW + x0 + xs;
    #pragma unroll
    for (int c = 0; c < CPT; c++) {
        float4 v;
        v.x = acc[c][0]; v.y = acc[c][1]; v.z = acc[c][2]; v.w = acc[c][3];
        *(float4*)(outp + (size_t)(c0 + ch * CPT + c) * HWSZ) = v;
    }
}

extern "C" void kernel_launch(void* const* d_in, const int* in_sizes, int n_in,
                              void* d_out, int out_size)
{
    const float* aff = (const float*)d_in[0];   // [4,169,192,192]
    const float* in2 = (const float*)d_in[1];   // [4,64,192,192]
    float* out = (float*)d_out;                 // [4,64,192,192]

    dim3 grid(12, 24, 4);   // (cgroup*xtile, ytile, batch) — cgroup fastest for aff L2 reuse
    dim3 block(16, 16);
    mxassemble_kernel<<<grid, block>>>(aff, in2, out);
}

// round 6
// speedup vs baseline: 1.5835x; 1.5835x over previous
#include <cuda_runtime.h>

// MxAssemble: out[b,c,y,x] = sum_{dy,dx in [0,13)} aff[b, dy*13+dx, y, x] * in2zp[b, c, y+dy-6, x+dx-6]
// B=4, D=169, C=64, H=W=192, fp32.
// f32x2-packed inner product; smem tile of in2 with column shift so compute
// reads are 4 aligned LDS.128 per (channel, dy).

#define BB   4
#define CC   64
#define HH   192
#define WW   192
#define WIN  13
#define DD   169
#define HWSZ (HH*WW)

#define TW    64     // x pixels per block
#define TH    8      // y rows per block
#define CBLK  16     // channels per block
#define CPT   8      // channels per thread
#define XR    4      // x pixels per thread
#define SROWS (TH+12)   // 20
#define SPITCH 80       // floats per smem row (320B, 16B aligned)
// smem col c  <->  global x = x0 - 6 + c ; compute for thread base xs reads cols xs..xs+15

typedef unsigned long long u64t;

__device__ __forceinline__ u64t ffma2(u64t a, u64t b, u64t c) {
    u64t d;
    asm("fma.rn.f32x2 %0, %1, %2, %3;" : "=l"(d) : "l"(a), "l"(b), "l"(c));
    return d;
}
__device__ __forceinline__ u64t packf2(float lo, float hi) {
    u64t d;
    asm("mov.b64 %0, {%1, %2};" : "=l"(d) : "f"(lo), "f"(hi));
    return d;
}
__device__ __forceinline__ void unpackf2(u64t v, float& lo, float& hi) {
    asm("mov.b64 {%0, %1}, %2;" : "=f"(lo), "=f"(hi) : "l"(v));
}

__global__ __launch_bounds__(256, 2)
void mxassemble_kernel(const float* __restrict__ aff,
                       const float* __restrict__ in2,
                       float* __restrict__ out)
{
    __shared__ __align__(16) float s[CBLK][SROWS][SPITCH];

    const int tx = threadIdx.x;      // 0..15  -> x group
    const int ty = threadIdx.y;      // 0..15
    const int yy = ty & 7;           // row within tile
    const int ch = ty >> 3;          // channel half (0/1)

    const int bx = blockIdx.x;       // 12 = 4 cgroups * 3 xtiles, cgroup fastest
    const int cg = bx & 3;
    const int xt = bx >> 2;
    const int yt = blockIdx.y;       // 0..23
    const int b  = blockIdx.z;       // 0..3

    const int x0 = xt * TW;
    const int y0 = yt * TH;
    const int c0 = cg * CBLK;

    // ---- cooperative smem fill -------------------------------------------
    // quads: 16 planes x 20 rows x 20 aligned global quads (gxq = x0-8+4q)
    // smem col for gx is gx - (x0-6); quad lands at c0q = 4q-2 (two STS.64).
    {
        const float* in2b = in2 + (size_t)b * CC * HWSZ;
        const int tid = ty * 16 + tx;
        #pragma unroll 1
        for (int idx = tid; idx < CBLK * SROWS * 20; idx += 256) {
            const int q   = idx % 20;
            const int t2  = idx / 20;
            const int rr  = t2 % 20;
            const int cc  = t2 / 20;
            const int gy  = y0 - 6 + rr;
            const int gxq = x0 - 8 + 4 * q;

            float4 v = make_float4(0.f, 0.f, 0.f, 0.f);
            if ((unsigned)gy < (unsigned)HH) {
                const float* src = in2b + (size_t)(c0 + cc) * HWSZ + gy * WW + gxq;
                if (gxq >= 0 && gxq <= WW - 4) {
                    v = *(const float4*)src;
                } else {
                    if ((unsigned)(gxq + 0) < (unsigned)WW) v.x = src[0];
                    if ((unsigned)(gxq + 1) < (unsigned)WW) v.y = src[1];
                    if ((unsigned)(gxq + 2) < (unsigned)WW) v.z = src[2];
                    if ((unsigned)(gxq + 3) < (unsigned)WW) v.w = src[3];
                }
            }
            const int c0q = 4 * q - 2;               // smem col of v.x
            float* dst = &s[cc][rr][0];
            if (c0q >= 0) *(float2*)(dst + c0q) = make_float2(v.x, v.y);
            *(float2*)(dst + c0q + 2) = make_float2(v.z, v.w);
        }
    }
    __syncthreads();

    // ---- main accumulation ------------------------------------------------
    u64t accA[CPT], accB[CPT];       // accA: outputs (xs, xs+1), accB: (xs+2, xs+3)
    #pragma unroll
    for (int c = 0; c < CPT; c++) { accA[c] = 0ull; accB[c] = 0ull; }

    const int xs = tx * XR;
    const float* affp = aff + (size_t)b * DD * HWSZ + (y0 + yy) * WW + x0 + xs;

    #pragma unroll 1
    for (int dy = 0; dy < WIN; dy++) {
        // aff operand pairs: ap[j].x = (a[j][x0..x1]), ap[j].y = (a[j][x2..x3])
        ulonglong2 ap[WIN];
        #pragma unroll
        for (int j = 0; j < WIN; j++)
            ap[j] = *(const ulonglong2*)(affp + (size_t)(dy * WIN + j) * HWSZ);

        #pragma unroll
        for (int c = 0; c < CPT; c++) {
            const float* srow = &s[ch * CPT + c][yy + dy][xs];
            // 4 aligned LDS.128: r[0..15]
            union { ulonglong2 u; float4 f; } Q[4];
            #pragma unroll
            for (int q = 0; q < 4; q++)
                Q[q].u = *(const ulonglong2*)(srow + 4 * q);

            u64t p[15];                       // p[k] = (r[k], r[k+1])
            #pragma unroll
            for (int q = 0; q < 4; q++) {
                p[4 * q]     = Q[q].u.x;      // (r0,r1) aligned -> free
                if (4 * q + 2 <= 14) p[4 * q + 2] = Q[q].u.y;
            }
            #pragma unroll
            for (int t = 0; t < 7; t++) {     // odd pairs: (r[2t+1], r[2t+2])
                const int k = 2 * t + 1;
                const float lo = (k & 2) ? Q[k >> 2].f.w : Q[k >> 2].f.y;
                const int k2 = k + 1;
                const float hi = (k2 & 2) ? Q[k2 >> 2].f.z : Q[k2 >> 2].f.x;
                p[k] = packf2(lo, hi);
            }

            #pragma unroll
            for (int j = 0; j < WIN; j++) {
                accA[c] = ffma2(ap[j].x, p[j],     accA[c]);
                accB[c] = ffma2(ap[j].y, p[j + 2], accB[c]);
            }
        }
    }

    // ---- write out --------------------------------------------------------
    float* outp = out + (size_t)b * CC * HWSZ + (y0 + yy) * WW + x0 + xs;
    #pragma unroll
    for (int c = 0; c < CPT; c++) {
        float4 v;
        unpackf2(accA[c], v.x, v.y);
        unpackf2(accB[c], v.z, v.w);
        *(float4*)(outp + (size_t)(c0 + ch * CPT + c) * HWSZ) = v;
    }
}

extern "C" void kernel_launch(void* const* d_in, const int* in_sizes, int n_in,
                              void* d_out, int out_size)
{
    const float* aff = (const float*)d_in[0];   // [4,169,192,192]
    const float* in2 = (const float*)d_in[1];   // [4,64,192,192]
    float* out = (float*)d_out;                 // [4,64,192,192]

    dim3 grid(12, 24, 4);   // (cgroup*xtile, ytile, batch) — cgroup fastest for aff L2 reuse
    dim3 block(16, 16);
    mxassemble_kernel<<<grid, block>>>(aff, in2, out);
}